// round 2
// baseline (speedup 1.0000x reference)
#include <cuda_runtime.h>
#include <math.h>

#define GN_N_NODES 200000
#define GN_N_FEAT 256

// Scratch (device globals — no allocations allowed)
__device__ float g_h[GN_N_NODES];    // x @ W
__device__ float g_dis[GN_N_NODES];  // deg, then rsqrt(deg) in place
__device__ int   g_is64;             // 1 if edge_index is int64, 0 if int32

// ---------------------------------------------------------------------------
// Kernel 0: detect edge_index dtype. If the buffer really is int64, every
// sampled 64-bit value is a valid node id in [0, N). If it's int32 data,
// a 64-bit read combines two indices -> almost surely out of range.
// ---------------------------------------------------------------------------
__global__ void k_detect(const long long* __restrict__ ei, int E, int N) {
    __shared__ int bad;
    if (threadIdx.x == 0) bad = 0;
    __syncthreads();
    int stride = E / 1024;
    for (int i = threadIdx.x; i < 1024; i += blockDim.x) {
        long long v = ei[(size_t)i * stride];
        if (v < 0 || v >= (long long)N) bad = 1;   // benign race, any write of 1 ok
    }
    __syncthreads();
    if (threadIdx.x == 0) g_is64 = bad ? 0 : 1;
}

// ---------------------------------------------------------------------------
// Kernel A: h[n] = dot(x[n,:], W), init deg[n]=1 (self loop), out[n]=0
// one warp per node, float4 loads (row = 1KB, perfectly coalesced)
// ---------------------------------------------------------------------------
__global__ void k_gemv_init(const float* __restrict__ x,
                            const float* __restrict__ W,
                            float* __restrict__ h,
                            float* __restrict__ deg,
                            float* __restrict__ out,
                            int n_nodes) {
    int warp = (blockIdx.x * blockDim.x + threadIdx.x) >> 5;
    int lane = threadIdx.x & 31;
    if (warp >= n_nodes) return;

    const float4* xr = reinterpret_cast<const float4*>(x + (size_t)warp * GN_N_FEAT);
    const float4* wv = reinterpret_cast<const float4*>(W);

    float s = 0.f;
#pragma unroll
    for (int i = 0; i < 2; i++) {
        float4 a = xr[lane + 32 * i];
        float4 b = __ldg(&wv[lane + 32 * i]);
        s += a.x * b.x + a.y * b.y + a.z * b.z + a.w * b.w;
    }
#pragma unroll
    for (int o = 16; o; o >>= 1) s += __shfl_down_sync(0xFFFFFFFFu, s, o);

    if (lane == 0) {
        h[warp]   = s;
        deg[warp] = 1.0f;   // self-loop weight
        out[warp] = 0.0f;
    }
}

// ---------------------------------------------------------------------------
// Kernel B: deg[col[e]] += attrs[e]
// ---------------------------------------------------------------------------
__global__ void k_deg(const void* __restrict__ ei,
                      const float* __restrict__ attrs,
                      float* __restrict__ deg,
                      int E) {
    int i = blockIdx.x * blockDim.x + threadIdx.x;
    if (i >= E) return;
    int c;
    if (g_is64) {
        c = (int)((const long long*)ei)[(size_t)E + i];
    } else {
        c = ((const int*)ei)[(size_t)E + i];
    }
    atomicAdd(&deg[c], attrs[i]);
}

// ---------------------------------------------------------------------------
// Kernel C: dis[n] = deg>0 ? rsqrt(deg) : 0   (in place)
// ---------------------------------------------------------------------------
__global__ void k_rsqrt(float* __restrict__ deg, int n_nodes) {
    int i = blockIdx.x * blockDim.x + threadIdx.x;
    if (i < n_nodes) {
        float d = deg[i];
        deg[i] = (d > 0.f) ? rsqrtf(d) : 0.f;
    }
}

// ---------------------------------------------------------------------------
// Kernel D: out[col] += dis[row] * attrs * dis[col] * h[row]
// dis/h are 800KB each -> L2-resident gathers
// ---------------------------------------------------------------------------
__global__ void k_msg(const void* __restrict__ ei,
                      const float* __restrict__ attrs,
                      const float* __restrict__ dis,
                      const float* __restrict__ h,
                      float* __restrict__ out,
                      int E) {
    int i = blockIdx.x * blockDim.x + threadIdx.x;
    if (i >= E) return;
    int r, c;
    if (g_is64) {
        const long long* p = (const long long*)ei;
        r = (int)p[i];
        c = (int)p[(size_t)E + i];
    } else {
        const int* p = (const int*)ei;
        r = p[i];
        c = p[(size_t)E + i];
    }
    float v = dis[r] * attrs[i] * dis[c] * h[r];
    atomicAdd(&out[c], v);
}

// ---------------------------------------------------------------------------
// Kernel E: add self loop + bias, apply Mish
// ---------------------------------------------------------------------------
__global__ void k_finish(float* __restrict__ out,
                         const float* __restrict__ dis,
                         const float* __restrict__ h,
                         const float* __restrict__ b,
                         int n_nodes) {
    int i = blockIdx.x * blockDim.x + threadIdx.x;
    if (i < n_nodes) {
        float d = dis[i];
        float t = out[i] + d * d * h[i] + b[0];
        float sp = (t > 20.f) ? t : log1pf(expf(t));
        out[i] = t * tanhf(sp);
    }
}

extern "C" void kernel_launch(void* const* d_in, const int* in_sizes, int n_in,
                              void* d_out, int out_size) {
    // --- identify inputs by element count (robust to ordering) ---
    // x: N*256 (largest), edge_index: 2E, attrs: E, W: 256, b: 1
    int ix = 0, ie = 1, ia = 2, iw = 3, ib = 4;
    {
        // find b (size 1) and W (size 256, but not the largest with 256 factor)
        long long best = -1;
        for (int i = 0; i < n_in; i++) if ((long long)in_sizes[i] > best) { best = in_sizes[i]; ix = i; }
        long long second = -1;
        for (int i = 0; i < n_in; i++) if (i != ix && (long long)in_sizes[i] > second) { second = in_sizes[i]; ie = i; }
        long long third = -1;
        for (int i = 0; i < n_in; i++) if (i != ix && i != ie && (long long)in_sizes[i] > third) { third = in_sizes[i]; ia = i; }
        long long fourth = -1;
        for (int i = 0; i < n_in; i++) if (i != ix && i != ie && i != ia && (long long)in_sizes[i] > fourth) { fourth = in_sizes[i]; iw = i; }
        for (int i = 0; i < n_in; i++) if (i != ix && i != ie && i != ia && i != iw) ib = i;
    }

    const float* x    = (const float*)d_in[ix];
    const void*  ei   = d_in[ie];
    const float* atts = (const float*)d_in[ia];
    const float* W    = (const float*)d_in[iw];
    const float* b    = (const float*)d_in[ib];
    float*       out  = (float*)d_out;

    const int E = in_sizes[ia];                 // 12.8M
    const int N = in_sizes[ix] / GN_N_FEAT;     // 200k

    float* h;   cudaGetSymbolAddress((void**)&h,   g_h);
    float* dis; cudaGetSymbolAddress((void**)&dis, g_dis);

    // 0: dtype detection (cheap, 1 block)
    k_detect<<<1, 256>>>((const long long*)ei, E, N);

    // A: GEMV + init
    {
        int threads = 256;
        int blocks = (N + 7) / 8;
        k_gemv_init<<<blocks, threads>>>(x, W, h, dis, out, N);
    }
    // B: degree scatter
    k_deg<<<(E + 255) / 256, 256>>>(ei, atts, dis, E);
    // C: rsqrt
    k_rsqrt<<<(N + 255) / 256, 256>>>(dis, N);
    // D: edge messages
    k_msg<<<(E + 255) / 256, 256>>>(ei, atts, dis, h, out, E);
    // E: self loop + bias + Mish
    k_finish<<<(N + 255) / 256, 256>>>(out, dis, h, b, N);
}

// round 3
// speedup vs baseline: 1.3365x; 1.3365x over previous
#include <cuda_runtime.h>
#include <math.h>

#define GN_N_NODES 200000
#define GN_N_FEAT 256

// Scratch (device globals — no allocations allowed)
__device__ float g_h[GN_N_NODES];    // x @ W
__device__ float g_dis[GN_N_NODES];  // deg, then rsqrt(deg) in place
__device__ float g_a[GN_N_NODES];    // dis * h   (scatter source)
__device__ int   g_is64;             // 1 if edge_index is int64, 0 if int32

// ---------------------------------------------------------------------------
// Kernel 0: detect edge_index dtype (int64 vs int32 stored in same buffer).
// ---------------------------------------------------------------------------
__global__ void k_detect(const long long* __restrict__ ei, int E, int N) {
    __shared__ int bad;
    if (threadIdx.x == 0) bad = 0;
    __syncthreads();
    int stride = E / 1024;
    for (int i = threadIdx.x; i < 1024; i += blockDim.x) {
        long long v = ei[(size_t)i * stride];
        if (v < 0 || v >= (long long)N) bad = 1;
    }
    __syncthreads();
    if (threadIdx.x == 0) g_is64 = bad ? 0 : 1;
}

// ---------------------------------------------------------------------------
// Kernel A: h[n] = dot(x[n,:], W), init deg[n]=1 (self loop), out[n]=0
// ---------------------------------------------------------------------------
__global__ void k_gemv_init(const float* __restrict__ x,
                            const float* __restrict__ W,
                            float* __restrict__ h,
                            float* __restrict__ deg,
                            float* __restrict__ out,
                            int n_nodes) {
    int warp = (blockIdx.x * blockDim.x + threadIdx.x) >> 5;
    int lane = threadIdx.x & 31;
    if (warp >= n_nodes) return;

    const float4* xr = reinterpret_cast<const float4*>(x + (size_t)warp * GN_N_FEAT);
    const float4* wv = reinterpret_cast<const float4*>(W);

    float s = 0.f;
#pragma unroll
    for (int i = 0; i < 2; i++) {
        float4 a = xr[lane + 32 * i];
        float4 b = __ldg(&wv[lane + 32 * i]);
        s += a.x * b.x + a.y * b.y + a.z * b.z + a.w * b.w;
    }
#pragma unroll
    for (int o = 16; o; o >>= 1) s += __shfl_down_sync(0xFFFFFFFFu, s, o);

    if (lane == 0) {
        h[warp]   = s;
        deg[warp] = 1.0f;   // self-loop weight
        out[warp] = 0.0f;
    }
}

// ---------------------------------------------------------------------------
// Kernel B: deg[col[e]] += attrs[e]   (2 edges / thread, vector loads)
// ---------------------------------------------------------------------------
__global__ void k_deg(const void* __restrict__ ei,
                      const float* __restrict__ attrs,
                      float* __restrict__ deg,
                      int E) {
    int i = blockIdx.x * blockDim.x + threadIdx.x;  // pair index
    int e = i << 1;
    if (e >= E) return;
    float2 w = reinterpret_cast<const float2*>(attrs)[i];
    int c0, c1;
    if (g_is64) {
        longlong2 c = reinterpret_cast<const longlong2*>(
            (const long long*)ei + E)[i];
        c0 = (int)c.x; c1 = (int)c.y;
    } else {
        int2 c = reinterpret_cast<const int2*>((const int*)ei + E)[i];
        c0 = c.x; c1 = c.y;
    }
    atomicAdd(&deg[c0], w.x);
    if (e + 1 < E) atomicAdd(&deg[c1], w.y);
}

// ---------------------------------------------------------------------------
// Kernel C: dis = deg>0 ? rsqrt(deg) : 0 ; a = dis*h
// ---------------------------------------------------------------------------
__global__ void k_rsqrt(float* __restrict__ deg,
                        const float* __restrict__ h,
                        float* __restrict__ a,
                        int n_nodes) {
    int i = blockIdx.x * blockDim.x + threadIdx.x;
    if (i < n_nodes) {
        float d = deg[i];
        float dis = (d > 0.f) ? rsqrtf(d) : 0.f;
        deg[i] = dis;
        a[i]   = dis * h[i];
    }
}

// ---------------------------------------------------------------------------
// Kernel D: out[col] += a[row] * attrs   (dis[col] factored out of the sum)
// One L2 gather per edge instead of four.
// ---------------------------------------------------------------------------
__global__ void k_msg(const void* __restrict__ ei,
                      const float* __restrict__ attrs,
                      const float* __restrict__ a,
                      float* __restrict__ out,
                      int E) {
    int i = blockIdx.x * blockDim.x + threadIdx.x;  // pair index
    int e = i << 1;
    if (e >= E) return;
    float2 w = reinterpret_cast<const float2*>(attrs)[i];
    int r0, r1, c0, c1;
    if (g_is64) {
        const long long* p = (const long long*)ei;
        longlong2 r = reinterpret_cast<const longlong2*>(p)[i];
        longlong2 c = reinterpret_cast<const longlong2*>(p + E)[i];
        r0 = (int)r.x; r1 = (int)r.y;
        c0 = (int)c.x; c1 = (int)c.y;
    } else {
        const int* p = (const int*)ei;
        int2 r = reinterpret_cast<const int2*>(p)[i];
        int2 c = reinterpret_cast<const int2*>(p + E)[i];
        r0 = r.x; r1 = r.y;
        c0 = c.x; c1 = c.y;
    }
    float v0 = a[r0] * w.x;
    atomicAdd(&out[c0], v0);
    if (e + 1 < E) {
        float v1 = a[r1] * w.y;
        atomicAdd(&out[c1], v1);
    }
}

// ---------------------------------------------------------------------------
// Kernel E: out = Mish(dis*(out + a) + b)   (self loop = dis*dis*h = dis*a)
// ---------------------------------------------------------------------------
__global__ void k_finish(float* __restrict__ out,
                         const float* __restrict__ dis,
                         const float* __restrict__ a,
                         const float* __restrict__ b,
                         int n_nodes) {
    int i = blockIdx.x * blockDim.x + threadIdx.x;
    if (i < n_nodes) {
        float t = dis[i] * (out[i] + a[i]) + b[0];
        float sp = (t > 20.f) ? t : log1pf(expf(t));
        out[i] = t * tanhf(sp);
    }
}

extern "C" void kernel_launch(void* const* d_in, const int* in_sizes, int n_in,
                              void* d_out, int out_size) {
    // identify inputs by element count (descending: x > edge > attrs > W > b)
    int ix = 0, ie = 1, ia = 2, iw = 3, ib = 4;
    {
        long long best = -1;
        for (int i = 0; i < n_in; i++) if ((long long)in_sizes[i] > best) { best = in_sizes[i]; ix = i; }
        long long second = -1;
        for (int i = 0; i < n_in; i++) if (i != ix && (long long)in_sizes[i] > second) { second = in_sizes[i]; ie = i; }
        long long third = -1;
        for (int i = 0; i < n_in; i++) if (i != ix && i != ie && (long long)in_sizes[i] > third) { third = in_sizes[i]; ia = i; }
        long long fourth = -1;
        for (int i = 0; i < n_in; i++) if (i != ix && i != ie && i != ia && (long long)in_sizes[i] > fourth) { fourth = in_sizes[i]; iw = i; }
        for (int i = 0; i < n_in; i++) if (i != ix && i != ie && i != ia && i != iw) ib = i;
    }

    const float* x    = (const float*)d_in[ix];
    const void*  ei   = d_in[ie];
    const float* atts = (const float*)d_in[ia];
    const float* W    = (const float*)d_in[iw];
    const float* b    = (const float*)d_in[ib];
    float*       out  = (float*)d_out;

    const int E = in_sizes[ia];                 // 12.8M
    const int N = in_sizes[ix] / GN_N_FEAT;     // 200k

    float* h;   cudaGetSymbolAddress((void**)&h,   g_h);
    float* dis; cudaGetSymbolAddress((void**)&dis, g_dis);
    float* a;   cudaGetSymbolAddress((void**)&a,   g_a);

    // 0: dtype detection (1 block, trivial)
    k_detect<<<1, 256>>>((const long long*)ei, E, N);

    // A: GEMV + init
    k_gemv_init<<<(N + 7) / 8, 256>>>(x, W, h, dis, out, N);

    // B: degree scatter (2 edges/thread)
    {
        int pairs = (E + 1) / 2;
        k_deg<<<(pairs + 255) / 256, 256>>>(ei, atts, dis, E);
    }
    // C: rsqrt + a = dis*h
    k_rsqrt<<<(N + 255) / 256, 256>>>(dis, h, a, N);

    // D: edge messages (2 edges/thread, 1 gather/edge)
    {
        int pairs = (E + 1) / 2;
        k_msg<<<(pairs + 255) / 256, 256>>>(ei, atts, a, out, E);
    }
    // E: scale + self loop + bias + Mish
    k_finish<<<(N + 255) / 256, 256>>>(out, dis, a, b, N);
}

// round 4
// speedup vs baseline: 1.3502x; 1.0103x over previous
#include <cuda_runtime.h>
#include <math.h>

#define GN_N_NODES 200000
#define GN_N_FEAT 256

// Scratch (device globals — zero-initialized BSS; no allocations allowed)
__device__ float g_h[GN_N_NODES];      // x @ W
__device__ float g_dis[GN_N_NODES];    // rsqrt(deg+1)
__device__ float g_a[GN_N_NODES];      // dis * h (scatter source)
__device__ float g_degacc[GN_N_NODES]; // edge-weight degree accumulator (kept zeroed between launches)
__device__ int   g_is64;               // 1 if edge_index is int64, 0 if int32

// ---------------------------------------------------------------------------
// Kernel 0: detect edge_index dtype (int64 vs int32 stored in same buffer).
// ---------------------------------------------------------------------------
__global__ void k_detect(const long long* __restrict__ ei, int E, int N) {
    __shared__ int bad;
    if (threadIdx.x == 0) bad = 0;
    __syncthreads();
    int stride = E / 1024;
    for (int i = threadIdx.x; i < 1024; i += blockDim.x) {
        long long v = ei[(size_t)i * stride];
        if (v < 0 || v >= (long long)N) bad = 1;
    }
    __syncthreads();
    if (threadIdx.x == 0) g_is64 = bad ? 0 : 1;
}

// ---------------------------------------------------------------------------
// Fused kernel 1: GEMV blocks + degree-scatter blocks interleaved (Bresenham),
// so DRAM-streaming GEMV overlaps LTS-atomic degree accumulation on every wave.
//   GEMV block: 8 warps, 1 node/warp:  h[n]=x[n,:]·W, out[n]=0
//   DEG block : 256 thr × 4 edges:     degacc[col[e]] += attrs[e]
// ---------------------------------------------------------------------------
__global__ void k_fused1(const float* __restrict__ x,
                         const float* __restrict__ W,
                         float* __restrict__ h,
                         float* __restrict__ degacc,
                         float* __restrict__ out,
                         int n_nodes,
                         const void* __restrict__ ei,
                         const float* __restrict__ attrs,
                         int E,
                         int nb_gemv, int nb_total) {
    long long b = blockIdx.x;
    long long before = b * nb_gemv / nb_total;
    long long incl   = (b + 1) * nb_gemv / nb_total;
    if (incl > before) {
        // ---- GEMV block (id = before) ----
        int node = (int)before * 8 + (threadIdx.x >> 5);
        int lane = threadIdx.x & 31;
        if (node >= n_nodes) return;

        const float4* xr = reinterpret_cast<const float4*>(x + (size_t)node * GN_N_FEAT);
        const float4* wv = reinterpret_cast<const float4*>(W);

        float s = 0.f;
#pragma unroll
        for (int i = 0; i < 2; i++) {
            float4 va = xr[lane + 32 * i];
            float4 vb = __ldg(&wv[lane + 32 * i]);
            s += va.x * vb.x + va.y * vb.y + va.z * vb.z + va.w * vb.w;
        }
#pragma unroll
        for (int o = 16; o; o >>= 1) s += __shfl_down_sync(0xFFFFFFFFu, s, o);

        if (lane == 0) {
            h[node]   = s;
            out[node] = 0.0f;
        }
    } else {
        // ---- DEG block (id = b - before), 4 edges/thread ----
        int did = (int)(b - before);
        long long e0 = ((long long)did * 256 + threadIdx.x) * 4;
        if (e0 >= E) return;
        if (e0 + 3 < E) {
            float4 w = *reinterpret_cast<const float4*>(attrs + e0);
            int c0, c1, c2, c3;
            if (g_is64) {
                const long long* p = (const long long*)ei + E;
                longlong2 ca = *reinterpret_cast<const longlong2*>(p + e0);
                longlong2 cb = *reinterpret_cast<const longlong2*>(p + e0 + 2);
                c0 = (int)ca.x; c1 = (int)ca.y; c2 = (int)cb.x; c3 = (int)cb.y;
            } else {
                const int* p = (const int*)ei + E;
                int4 c = *reinterpret_cast<const int4*>(p + e0);
                c0 = c.x; c1 = c.y; c2 = c.z; c3 = c.w;
            }
            atomicAdd(&degacc[c0], w.x);
            atomicAdd(&degacc[c1], w.y);
            atomicAdd(&degacc[c2], w.z);
            atomicAdd(&degacc[c3], w.w);
        } else {
            for (long long e = e0; e < E; e++) {
                int c = g_is64 ? (int)((const long long*)ei)[E + e]
                               : ((const int*)ei)[E + e];
                atomicAdd(&degacc[c], attrs[e]);
            }
        }
    }
}

// ---------------------------------------------------------------------------
// Kernel C: dis = rsqrt(degacc + 1) ; a = dis*h ; re-zero degacc for next replay
// (deg+1 >= 1 always, since attrs >= 0 and self-loop weight is 1)
// ---------------------------------------------------------------------------
__global__ void k_rsqrt(float* __restrict__ degacc,
                        float* __restrict__ dis,
                        const float* __restrict__ h,
                        float* __restrict__ a,
                        int n_nodes) {
    int i = blockIdx.x * blockDim.x + threadIdx.x;
    if (i < n_nodes) {
        float d = degacc[i] + 1.0f;
        degacc[i] = 0.0f;                 // keep accumulator zeroed
        float di = rsqrtf(d);
        dis[i] = di;
        a[i]   = di * h[i];
    }
}

// ---------------------------------------------------------------------------
// Kernel D: out[col] += a[row] * attrs   (4 edges/thread, 1 gather/edge)
// ---------------------------------------------------------------------------
__global__ void k_msg(const void* __restrict__ ei,
                      const float* __restrict__ attrs,
                      const float* __restrict__ a,
                      float* __restrict__ out,
                      int E) {
    long long e0 = ((long long)blockIdx.x * blockDim.x + threadIdx.x) * 4;
    if (e0 >= E) return;
    if (e0 + 3 < E) {
        float4 w = *reinterpret_cast<const float4*>(attrs + e0);
        int r0, r1, r2, r3, c0, c1, c2, c3;
        if (g_is64) {
            const long long* pr = (const long long*)ei;
            const long long* pc = pr + E;
            longlong2 ra = *reinterpret_cast<const longlong2*>(pr + e0);
            longlong2 rb = *reinterpret_cast<const longlong2*>(pr + e0 + 2);
            longlong2 ca = *reinterpret_cast<const longlong2*>(pc + e0);
            longlong2 cb = *reinterpret_cast<const longlong2*>(pc + e0 + 2);
            r0 = (int)ra.x; r1 = (int)ra.y; r2 = (int)rb.x; r3 = (int)rb.y;
            c0 = (int)ca.x; c1 = (int)ca.y; c2 = (int)cb.x; c3 = (int)cb.y;
        } else {
            const int* pr = (const int*)ei;
            const int* pc = pr + E;
            int4 r = *reinterpret_cast<const int4*>(pr + e0);
            int4 c = *reinterpret_cast<const int4*>(pc + e0);
            r0 = r.x; r1 = r.y; r2 = r.z; r3 = r.w;
            c0 = c.x; c1 = c.y; c2 = c.z; c3 = c.w;
        }
        float v0 = a[r0] * w.x;
        float v1 = a[r1] * w.y;
        float v2 = a[r2] * w.z;
        float v3 = a[r3] * w.w;
        atomicAdd(&out[c0], v0);
        atomicAdd(&out[c1], v1);
        atomicAdd(&out[c2], v2);
        atomicAdd(&out[c3], v3);
    } else {
        for (long long e = e0; e < E; e++) {
            int r, c;
            if (g_is64) {
                r = (int)((const long long*)ei)[e];
                c = (int)((const long long*)ei)[E + e];
            } else {
                r = ((const int*)ei)[e];
                c = ((const int*)ei)[E + e];
            }
            atomicAdd(&out[c], a[r] * attrs[e]);
        }
    }
}

// ---------------------------------------------------------------------------
// Kernel E: out = Mish(dis*(out + a) + b)   (self loop = dis*dis*h = dis*a)
// ---------------------------------------------------------------------------
__global__ void k_finish(float* __restrict__ out,
                         const float* __restrict__ dis,
                         const float* __restrict__ a,
                         const float* __restrict__ b,
                         int n_nodes) {
    int i = blockIdx.x * blockDim.x + threadIdx.x;
    if (i < n_nodes) {
        float t = dis[i] * (out[i] + a[i]) + b[0];
        float sp = (t > 20.f) ? t : log1pf(expf(t));
        out[i] = t * tanhf(sp);
    }
}

extern "C" void kernel_launch(void* const* d_in, const int* in_sizes, int n_in,
                              void* d_out, int out_size) {
    // identify inputs by element count (descending: x > edge > attrs > W > b)
    int ix = 0, ie = 1, ia = 2, iw = 3, ib = 4;
    {
        long long best = -1;
        for (int i = 0; i < n_in; i++) if ((long long)in_sizes[i] > best) { best = in_sizes[i]; ix = i; }
        long long second = -1;
        for (int i = 0; i < n_in; i++) if (i != ix && (long long)in_sizes[i] > second) { second = in_sizes[i]; ie = i; }
        long long third = -1;
        for (int i = 0; i < n_in; i++) if (i != ix && i != ie && (long long)in_sizes[i] > third) { third = in_sizes[i]; ia = i; }
        long long fourth = -1;
        for (int i = 0; i < n_in; i++) if (i != ix && i != ie && i != ia && (long long)in_sizes[i] > fourth) { fourth = in_sizes[i]; iw = i; }
        for (int i = 0; i < n_in; i++) if (i != ix && i != ie && i != ia && i != iw) ib = i;
    }

    const float* x    = (const float*)d_in[ix];
    const void*  ei   = d_in[ie];
    const float* atts = (const float*)d_in[ia];
    const float* W    = (const float*)d_in[iw];
    const float* b    = (const float*)d_in[ib];
    float*       out  = (float*)d_out;

    const int E = in_sizes[ia];                 // 12.8M
    const int N = in_sizes[ix] / GN_N_FEAT;     // 200k

    float* h;    cudaGetSymbolAddress((void**)&h,    g_h);
    float* dis;  cudaGetSymbolAddress((void**)&dis,  g_dis);
    float* a;    cudaGetSymbolAddress((void**)&a,    g_a);
    float* dacc; cudaGetSymbolAddress((void**)&dacc, g_degacc);

    // 0: dtype detection (1 block, trivial)
    k_detect<<<1, 256>>>((const long long*)ei, E, N);

    // 1: fused GEMV + degree scatter (interleaved block types)
    {
        int nb_gemv = (N + 7) / 8;
        int nb_deg  = (E + 1023) / 1024;
        int nb_total = nb_gemv + nb_deg;
        k_fused1<<<nb_total, 256>>>(x, W, h, dacc, out, N, ei, atts, E,
                                    nb_gemv, nb_total);
    }
    // 2: rsqrt + a = dis*h (+ re-zero deg accumulator)
    k_rsqrt<<<(N + 255) / 256, 256>>>(dacc, dis, h, a, N);

    // 3: edge messages (4 edges/thread, 1 gather/edge)
    {
        long long quads = ((long long)E + 3) / 4;
        int blocks = (int)((quads + 255) / 256);
        k_msg<<<blocks, 256>>>(ei, atts, a, out, E);
    }
    // 4: scale + self loop + bias + Mish
    k_finish<<<(N + 255) / 256, 256>>>(out, dis, a, b, N);
}